// round 10
// baseline (speedup 1.0000x reference)
#include <cuda_runtime.h>
#include <cstdint>

#define D_MODEL 1024
#define FF      1024
#define NB      8
#define SEQ     2048
#define MTOT    (NB * SEQ)            // 16384
#define ATTN_SCALE 0.03125f

// ---------------------------------------------------------------------------
// Scratch (device globals: allocation-free)
// ---------------------------------------------------------------------------
__device__ float g_SR[(size_t)MTOT * D_MODEL];       // 64 MiB  seq, tf32-rounded
__device__ float g_WR[(size_t)3 * FF * D_MODEL];     // 12 MiB  Wq/Wk/Wv rounded
__device__ float g_Q [(size_t)MTOT * FF];            // 64 MiB
__device__ float g_K [(size_t)MTOT * FF];            // 64 MiB
__device__ float g_V [(size_t)MTOT * FF];            // 64 MiB
__device__ float g_S [(size_t)NB * SEQ * SEQ];       // 128 MiB

// ---------------------------------------------------------------------------
// Helpers
// ---------------------------------------------------------------------------
__device__ __forceinline__ float tf32r(float x) {
    uint32_t u; asm("cvt.rna.tf32.f32 %0, %1;" : "=r"(u) : "f"(x));
    return __uint_as_float(u);
}
__device__ __forceinline__ uint32_t smem_u32(const void* p) {
    uint32_t a;
    asm("{ .reg .u64 t; cvta.to.shared.u64 t, %1; cvt.u32.u64 %0, t; }" : "=r"(a) : "l"(p));
    return a;
}
__device__ __forceinline__ void cp16(uint32_t dst, const void* src) {
    asm volatile("cp.async.cg.shared.global [%0], [%1], 16;" :: "r"(dst), "l"(src) : "memory");
}
__device__ __forceinline__ void cp_commit() { asm volatile("cp.async.commit_group;" ::: "memory"); }
__device__ __forceinline__ void cp_wait0()  { asm volatile("cp.async.wait_group 0;" ::: "memory"); }
__device__ __forceinline__ uint32_t lds32(uint32_t a) {
    uint32_t v; asm("ld.shared.b32 %0, [%1];" : "=r"(v) : "r"(a));
    return v;
}
__device__ __forceinline__ void mma8(float* c, const uint32_t* a, const uint32_t* b) {
    asm volatile(
        "mma.sync.aligned.m16n8k8.row.col.f32.tf32.tf32.f32 "
        "{%0,%1,%2,%3}, {%4,%5,%6,%7}, {%8,%9}, {%0,%1,%2,%3};\n"
        : "+f"(c[0]), "+f"(c[1]), "+f"(c[2]), "+f"(c[3])
        : "r"(a[0]), "r"(a[1]), "r"(a[2]), "r"(a[3]), "r"(b[0]), "r"(b[1]));
}

// Per-z operand selection (for the fused QKV projection launch)
struct Ptrs { const float* B; const float* bias; float* C; float scale; };
struct Sel  { Ptrs p[3]; };

// ---------------------------------------------------------------------------
// TF32 GEMM v5 (persistent tiles): C[M,N] = A[M,K]*op(B) (+bias)*scale.
//   BT=true : B[N,K] row-major (C = A B^T)    -- proj, QK^T
//   BT=false: B[K,N] row-major (C = A B)      -- PV
// CTA tile 128 x BNT x 64, 8 warps (warp grid 2x4, warp tile 64 x BNT/4).
// Stage = two BK=32 sub-tiles, 2-stage cp.async ring. Persistent: each CTA
// loops tiles t = bid, bid+grid, ...; at a tile's last k-iter it prefetches
// the NEXT tile's stage 0, so the pipeline never drains (NK even => parity ok).
// Tile id t -> x = t%TX (n-block), y = (t/TX)%TY (m-block), z = t/(TX*TY).
// fused=1: z selects sel.p[z] (strides sA/sB/sC must be 0 then).
// ---------------------------------------------------------------------------
constexpr int BM = 128, BK = 64, STG = 2;
constexpr int A_SUB = BM * 32 * 4;            // 16384 per sub-tile

template <bool BT, int BNT>
__global__ void __launch_bounds__(256)
gemm5(const float* __restrict__ A, Sel sel, int fused,
      int K, int ldb, int ldc,
      long long sA, long long sB, long long sC,
      int round_out, int TX, int TY, int ntiles)
{
    constexpr int NI     = BNT / 32;          // n8 blocks per warp
    constexpr int WN     = BNT / 4;           // warp n tile
    constexpr int CPR    = BNT / 4;           // NN 16B-chunks per smem row
    constexpr int BNN_LD = BNT + 8;
    constexpr int B_SUB  = BT ? BNT * 128 : 32 * BNN_LD * 4;
    constexpr int STGB   = 2 * A_SUB + 2 * B_SUB;

    extern __shared__ char smp[];
    const uint32_t sb = smem_u32(smp);
    const int tid = threadIdx.x, lane = tid & 31, warp = tid >> 5;
    const int gid = lane >> 2, tig = lane & 3;
    const int wm = (warp & 1) * 64, wn = (warp >> 1) * WN;
    const int stride = gridDim.x;

    // ---- tile-invariant, tid-derived offsets ----
    uint32_t dA[4]; int baseA[4];
    #pragma unroll
    for (int i = 0; i < 4; i++) {
        int id = tid + i * 256, r = id >> 3, c = id & 7;
        dA[i] = (uint32_t)(r * 128 + ((c ^ (r & 7)) * 16));
        baseA[i] = r * K + c * 4;
    }
    uint32_t dB[NI]; int baseB[NI];
    #pragma unroll
    for (int i = 0; i < NI; i++) {
        int id = tid + i * 256;
        if (BT) {
            int r = id >> 3, c = id & 7;
            dB[i] = (uint32_t)(r * 128 + ((c ^ (r & 7)) * 16));
            baseB[i] = r * ldb + c * 4;
        } else {
            int kr = id / CPR, c = id % CPR;
            dB[i] = (uint32_t)(kr * (BNN_LD * 4) + c * 16);
            baseB[i] = kr * ldb + c * 4;
        }
    }

    // ---- per-tile load pointers (advanced early for cross-tile prefetch) ----
    const float* APtr = A;
    const float* BPtr = A;
    auto decode_load = [&](int t) {
        int x = t % TX, yz = t / TX, y = yz % TY, z = yz / TY;
        const Ptrs pp = sel.p[fused ? z : 0];
        APtr = A + (long long)z * sA + (long long)(y * BM) * K;
        BPtr = BT ? (pp.B + (long long)z * sB + (long long)(x * BNT) * ldb)
                  : (pp.B + (long long)z * sB + (x * BNT));
    };
    auto loads = [&](int kt) {                 // kt = 64-wide chunk index
        const uint32_t st = sb + (kt & 1) * STGB;
        #pragma unroll
        for (int s = 0; s < 2; s++) {
            const int kof = kt * BK + s * 32;
            const uint32_t sa = st + s * A_SUB;
            #pragma unroll
            for (int i = 0; i < 4; i++) cp16(sa + dA[i], APtr + kof + baseA[i]);
            const float* Bk = BT ? (BPtr + kof) : (BPtr + (long long)kof * ldb);
            const uint32_t sbB = st + 2 * A_SUB + s * B_SUB;
            #pragma unroll
            for (int i = 0; i < NI; i++) cp16(sbB + dB[i], Bk + baseB[i]);
        }
        cp_commit();
    };

    uint32_t af[2][4][4], bf[2][NI][2];

    // ks in 0..7 -> sub-tile ks>>2, k4 = ks&3 within sub
    auto lfA = [&](uint32_t st, int ks, uint32_t f[4][4]) {
        const uint32_t sa = st + (ks >> 2) * A_SUB;
        const int k4 = ks & 3;
        const uint32_t ch0 = ((uint32_t)(2 * k4) ^ (uint32_t)gid) * 16 + tig * 4;
        const uint32_t ch1 = ((uint32_t)(2 * k4 + 1) ^ (uint32_t)gid) * 16 + tig * 4;
        #pragma unroll
        for (int mi = 0; mi < 4; mi++) {
            const uint32_t rb = sa + (wm + mi * 16 + gid) * 128;
            f[mi][0] = lds32(rb + ch0);
            f[mi][1] = lds32(rb + 8 * 128 + ch0);
            f[mi][2] = lds32(rb + ch1);
            f[mi][3] = lds32(rb + 8 * 128 + ch1);
        }
    };
    auto lfB = [&](uint32_t st, int ks, uint32_t f[NI][2]) {
        const uint32_t sbB = st + 2 * A_SUB + (ks >> 2) * B_SUB;
        const int k4 = ks & 3;
        if (BT) {
            const uint32_t ch0 = ((uint32_t)(2 * k4) ^ (uint32_t)gid) * 16 + tig * 4;
            const uint32_t ch1 = ((uint32_t)(2 * k4 + 1) ^ (uint32_t)gid) * 16 + tig * 4;
            #pragma unroll
            for (int ni = 0; ni < NI; ni++) {
                const uint32_t rb = sbB + (wn + ni * 8 + gid) * 128;
                f[ni][0] = lds32(rb + ch0);
                f[ni][1] = lds32(rb + ch1);
            }
        } else {
            const uint32_t rb = sbB + (8 * k4 + tig) * (BNN_LD * 4) + (wn + gid) * 4;
            #pragma unroll
            for (int ni = 0; ni < NI; ni++) {
                f[ni][0] = lds32(rb + ni * 32);
                f[ni][1] = lds32(rb + 4 * (BNN_LD * 4) + ni * 32);
            }
        }
    };

    const int NK = K / BK;
    int t = blockIdx.x;
    if (t < ntiles) { decode_load(t); loads(0); }

    for (; t < ntiles; t += stride) {
        // epilogue metadata for the CURRENT tile (load ptrs may advance early)
        const int x = t % TX, yz = t / TX, y = yz % TY, z = yz / TY;
        const Ptrs pm = sel.p[fused ? z : 0];
        const int m0 = y * BM, n0 = x * BNT;
        float*       Cb   = pm.C + (long long)z * sC;
        const float* bias = pm.bias;
        const float  scale = pm.scale;

        float acc[4][NI][4];
        #pragma unroll
        for (int i = 0; i < 4; i++)
            #pragma unroll
            for (int j = 0; j < NI; j++)
                #pragma unroll
                for (int l = 0; l < 4; l++) acc[i][j][l] = 0.f;

        for (int kt = 0; kt < NK; kt++) {
            cp_wait0();                        // stage kt landed
            __syncthreads();                   // all warps done with other buffer

            const uint32_t st = sb + (kt & 1) * STGB;

            lfA(st, 0, af[0]); lfB(st, 0, bf[0]);   // frag buffer 0 first
            if (kt + 1 < NK) loads(kt + 1);
            else if (t + stride < ntiles) {          // cross-tile prefetch
                decode_load(t + stride);             // NK even -> lands in buf 0
                loads(0);
            } else cp_commit();

            #pragma unroll
            for (int ks = 0; ks < 8; ks++) {
                const int cur = ks & 1, nxt = cur ^ 1;
                if (ks < 7) { lfA(st, ks + 1, af[nxt]); lfB(st, ks + 1, bf[nxt]); }
                #pragma unroll
                for (int mi = 0; mi < 4; mi++)
                    #pragma unroll
                    for (int ni = 0; ni < NI; ni++)
                        mma8(acc[mi][ni], af[cur][mi], bf[cur][ni]);
            }
        }

        // ---- epilogue: bias + scale + optional tf32 round, float2 stores ----
        #pragma unroll
        for (int mi = 0; mi < 4; mi++) {
            const int r = m0 + wm + mi * 16 + gid;
            #pragma unroll
            for (int ni = 0; ni < NI; ni++) {
                const int c = n0 + wn + ni * 8 + tig * 2;
                float b0 = 0.f, b1 = 0.f;
                if (bias) { b0 = bias[c]; b1 = bias[c + 1]; }
                float v0 = (acc[mi][ni][0] + b0) * scale;
                float v1 = (acc[mi][ni][1] + b1) * scale;
                float v2 = (acc[mi][ni][2] + b0) * scale;
                float v3 = (acc[mi][ni][3] + b1) * scale;
                if (round_out) { v0 = tf32r(v0); v1 = tf32r(v1); v2 = tf32r(v2); v3 = tf32r(v3); }
                *(float2*)(Cb + (long long)r * ldc + c)       = make_float2(v0, v1);
                *(float2*)(Cb + (long long)(r + 8) * ldc + c) = make_float2(v2, v3);
            }
        }
    }
}

constexpr int SM_TN256 = STG * (2 * A_SUB + 2 * 256 * 128);          // 196608
constexpr int SM_NN128 = STG * (2 * A_SUB + 2 * 32 * (128 + 8) * 4); // 135168

// ---------------------------------------------------------------------------
// Fused tf32 rounding of seq + Wq + Wk + Wv (single launch)
// ---------------------------------------------------------------------------
__global__ void __launch_bounds__(256)
round_all(const float4* __restrict__ seq, const float4* __restrict__ wq,
          const float4* __restrict__ wk,  const float4* __restrict__ wv,
          float4* __restrict__ sr, float4* __restrict__ wr)
{
    constexpr int NSEQ = MTOT * D_MODEL / 4;     // 4194304
    constexpr int NW   = FF * D_MODEL / 4;       // 262144
    constexpr int TOT  = NSEQ + 3 * NW;
    for (int i = blockIdx.x * 256 + threadIdx.x; i < TOT; i += gridDim.x * 256) {
        float4 v;
        float4* dst;
        if (i < NSEQ) { v = seq[i]; dst = sr + i; }
        else {
            int j = i - NSEQ, w = j / NW, o = j - w * NW;
            v = (w == 0) ? wq[o] : (w == 1) ? wk[o] : wv[o];
            dst = wr + j;
        }
        v.x = tf32r(v.x); v.y = tf32r(v.y); v.z = tf32r(v.z); v.w = tf32r(v.w);
        *dst = v;
    }
}

// ---------------------------------------------------------------------------
// Row softmax over 2048 cols; output tf32-rounded (feeds PV GEMM).
// ---------------------------------------------------------------------------
__global__ void __launch_bounds__(256)
softmax_tf32(float* __restrict__ S)
{
    __shared__ float red[8];
    float* row = S + (long long)blockIdx.x * SEQ;
    const int tid = threadIdx.x;

    float4 a = ((float4*)row)[tid];
    float4 b = ((float4*)row)[tid + 256];

    float m = fmaxf(fmaxf(fmaxf(a.x, a.y), fmaxf(a.z, a.w)),
                    fmaxf(fmaxf(b.x, b.y), fmaxf(b.z, b.w)));
    #pragma unroll
    for (int o = 16; o > 0; o >>= 1) m = fmaxf(m, __shfl_xor_sync(0xffffffffu, m, o));
    if ((tid & 31) == 0) red[tid >> 5] = m;
    __syncthreads();
    m = red[0];
    #pragma unroll
    for (int i = 1; i < 8; i++) m = fmaxf(m, red[i]);
    __syncthreads();

    a.x = __expf(a.x - m); a.y = __expf(a.y - m); a.z = __expf(a.z - m); a.w = __expf(a.w - m);
    b.x = __expf(b.x - m); b.y = __expf(b.y - m); b.z = __expf(b.z - m); b.w = __expf(b.w - m);
    float s = a.x + a.y + a.z + a.w + b.x + b.y + b.z + b.w;
    #pragma unroll
    for (int o = 16; o > 0; o >>= 1) s += __shfl_xor_sync(0xffffffffu, s, o);
    if ((tid & 31) == 0) red[tid >> 5] = s;
    __syncthreads();
    s = red[0] + red[1] + red[2] + red[3] + red[4] + red[5] + red[6] + red[7];
    const float inv = 1.0f / s;

    a.x = tf32r(a.x * inv); a.y = tf32r(a.y * inv); a.z = tf32r(a.z * inv); a.w = tf32r(a.w * inv);
    b.x = tf32r(b.x * inv); b.y = tf32r(b.y * inv); b.z = tf32r(b.z * inv); b.w = tf32r(b.w * inv);
    ((float4*)row)[tid]       = a;
    ((float4*)row)[tid + 256] = b;
}

// ---------------------------------------------------------------------------
// kernel_launch — graph-capturable, allocation-free.
// Inputs: 0=sequence, 1=Wq, 2=bq, 3=Wk, 4=bk, 5=Wv, 6=bv. Output fp32.
// ---------------------------------------------------------------------------
extern "C" void kernel_launch(void* const* d_in, const int* in_sizes, int n_in,
                              void* d_out, int out_size)
{
    const float* seq = (const float*)d_in[0];
    const float* Wq  = (const float*)d_in[1];
    const float* bq  = (const float*)d_in[2];
    const float* Wk  = (const float*)d_in[3];
    const float* bk  = (const float*)d_in[4];
    const float* Wv  = (const float*)d_in[5];
    const float* bv  = (const float*)d_in[6];
    float* out = (float*)d_out;

    float *SR, *WR, *Qp, *Kp, *Vp, *Sp;
    cudaGetSymbolAddress((void**)&SR, g_SR);
    cudaGetSymbolAddress((void**)&WR, g_WR);
    cudaGetSymbolAddress((void**)&Qp, g_Q);
    cudaGetSymbolAddress((void**)&Kp, g_K);
    cudaGetSymbolAddress((void**)&Vp, g_V);
    cudaGetSymbolAddress((void**)&Sp, g_S);

    cudaFuncSetAttribute(gemm5<true, 256>,  cudaFuncAttributeMaxDynamicSharedMemorySize, SM_TN256);
    cudaFuncSetAttribute(gemm5<false, 128>, cudaFuncAttributeMaxDynamicSharedMemorySize, SM_NN128);

    int nsm = 148, dev = 0;
    cudaGetDevice(&dev);
    cudaDeviceGetAttribute(&nsm, cudaDevAttrMultiProcessorCount, dev);

    const dim3 blk(256);
    const size_t WSZ = (size_t)FF * D_MODEL;

    // 0) fused tf32 rounding of all inputs
    round_all<<<2048, blk>>>((const float4*)seq, (const float4*)Wq,
                             (const float4*)Wk, (const float4*)Wv,
                             (float4*)SR, (float4*)WR);

    // 1) fused QKV projections: tiles (x=4, y=128, z=3) = 1536, persistent
    {
        Sel s;
        s.p[0] = { WR + 0 * WSZ, bq, Qp, ATTN_SCALE };
        s.p[1] = { WR + 1 * WSZ, bk, Kp, 1.0f };
        s.p[2] = { WR + 2 * WSZ, bv, Vp, 1.0f };
        const int TXp = FF / 256, TYp = MTOT / BM, NT = TXp * TYp * 3;
        gemm5<true, 256><<<(NT < nsm ? NT : nsm), blk, SM_TN256>>>(
            SR, s, 1, D_MODEL, D_MODEL, FF, 0, 0, 0, 1, TXp, TYp, NT);
    }

    const long long sQK = (long long)SEQ * FF;
    const long long sS  = (long long)SEQ * SEQ;

    // 2) scores: per batch [2048,2048] = Q @ K^T; tiles (8,16,8) = 1024
    {
        Sel s; s.p[0] = { Kp, nullptr, Sp, 1.0f };
        const int TXq = SEQ / 256, TYq = SEQ / BM, NT = TXq * TYq * NB;
        gemm5<true, 256><<<(NT < nsm ? NT : nsm), blk, SM_TN256>>>(
            Qp, s, 0, FF, FF, SEQ, sQK, sQK, sS, 0, TXq, TYq, NT);
    }

    // 3) softmax (rounds P to tf32)
    softmax_tf32<<<MTOT, blk>>>(Sp);

    // 4) output: per batch [2048,1024] = P @ V; tiles (8,16,8) = 1024 @ BN=128
    {
        Sel s; s.p[0] = { Vp, nullptr, out, 1.0f };
        const int TXo = FF / 128, TYo = SEQ / BM, NT = TXo * TYo * NB;
        gemm5<false, 128><<<(NT < nsm ? NT : nsm), blk, SM_NN128>>>(
            Sp, s, 0, SEQ, FF, FF, sS, sQK, sQK, 0, TXo, TYo, NT);
    }
}

// round 12
// speedup vs baseline: 1.1032x; 1.1032x over previous
#include <cuda_runtime.h>
#include <cstdint>

#define D_MODEL 1024
#define FF      1024
#define NB      8
#define SEQ     2048
#define MTOT    (NB * SEQ)            // 16384
#define ATTN_SCALE 0.03125f

// ---------------------------------------------------------------------------
// Scratch (device globals: allocation-free)
// ---------------------------------------------------------------------------
__device__ float g_SR[(size_t)MTOT * D_MODEL];       // 64 MiB  seq, tf32-rounded
__device__ float g_WR[(size_t)3 * FF * D_MODEL];     // 12 MiB  Wq/Wk/Wv rounded
__device__ float g_Q [(size_t)MTOT * FF];            // 64 MiB
__device__ float g_K [(size_t)MTOT * FF];            // 64 MiB
__device__ float g_V [(size_t)MTOT * FF];            // 64 MiB
__device__ float g_S [(size_t)NB * SEQ * SEQ];       // 128 MiB

// ---------------------------------------------------------------------------
// Helpers
// ---------------------------------------------------------------------------
__device__ __forceinline__ float tf32r(float x) {
    uint32_t u; asm("cvt.rna.tf32.f32 %0, %1;" : "=r"(u) : "f"(x));
    return __uint_as_float(u);
}
__device__ __forceinline__ uint32_t smem_u32(const void* p) {
    uint32_t a;
    asm("{ .reg .u64 t; cvta.to.shared.u64 t, %1; cvt.u32.u64 %0, t; }" : "=r"(a) : "l"(p));
    return a;
}
__device__ __forceinline__ void cp16(uint32_t dst, const void* src) {
    asm volatile("cp.async.cg.shared.global [%0], [%1], 16;" :: "r"(dst), "l"(src) : "memory");
}
__device__ __forceinline__ void cp_commit() { asm volatile("cp.async.commit_group;" ::: "memory"); }
__device__ __forceinline__ void cp_wait1()  { asm volatile("cp.async.wait_group 1;" ::: "memory"); }
__device__ __forceinline__ uint32_t lds32(uint32_t a) {
    uint32_t v; asm("ld.shared.b32 %0, [%1];" : "=r"(v) : "r"(a));
    return v;
}
__device__ __forceinline__ void mma8(float* c, const uint32_t* a, const uint32_t* b) {
    asm volatile(
        "mma.sync.aligned.m16n8k8.row.col.f32.tf32.tf32.f32 "
        "{%0,%1,%2,%3}, {%4,%5,%6,%7}, {%8,%9}, {%0,%1,%2,%3};\n"
        : "+f"(c[0]), "+f"(c[1]), "+f"(c[2]), "+f"(c[3])
        : "r"(a[0]), "r"(a[1]), "r"(a[2]), "r"(a[3]), "r"(b[0]), "r"(b[1]));
}

// Per-z operand selection (for the fused QKV projection launch)
struct Ptrs { const float* B; const float* bias; float* C; float scale; };
struct Sel  { Ptrs p[3]; };

// ---------------------------------------------------------------------------
// TF32 GEMM v6 (occupancy-2): C[M,N] = A[M,K]*op(B) (+bias)*scale.
//   BT=true : B[N,K] row-major (C = A B^T)    -- proj, QK^T
//   BT=false: B[K,N] row-major (C = A B)      -- PV
// CTA = 128 threads (4 warps, 2x2 warp grid), tile 128x128x32, warp tile
// 64x64 (same per-warp shape as v4/v5). 3-stage cp.async ring, 2 CTAs/SM:
// the second CTA covers this CTA's wait/barrier/warm-up serialization.
// TN smem: 128B rows, 16B-chunk XOR swizzle. NN B smem: [32][136] padded.
// fused=1: blockIdx.z selects sel.p[z] (strides sA/sB/sC are 0 then).
// ---------------------------------------------------------------------------
constexpr int BM = 128, BN = 128, BK = 32, STG = 3;
constexpr int A_BY   = BM * BK * 4;          // 16384
constexpr int BNN_LD = BN + 8;               // 136 floats per NN row
constexpr int BTN_BY = BN * 128;             // 16384
constexpr int BNN_BY = BK * BNN_LD * 4;      // 17408

template <bool BT>
__global__ void __launch_bounds__(128, 2)
gemm6(const float* __restrict__ A, Sel sel, int fused,
      int K, int ldb, int ldc,
      long long sA, long long sB, long long sC,
      int round_out)
{
    constexpr int NI   = 8;                   // n8 blocks per warp (64/8)
    constexpr int B_BY = BT ? BTN_BY : BNN_BY;
    constexpr int STGB = A_BY + B_BY;

    extern __shared__ char smp[];
    const uint32_t sb = smem_u32(smp);
    const int tid = threadIdx.x, lane = tid & 31, warp = tid >> 5;
    const int gid = lane >> 2, tig = lane & 3;
    const int wm = (warp & 1) * 64, wn = (warp >> 1) * 64;
    const int m0 = blockIdx.y * BM, n0 = blockIdx.x * BN;
    const int z  = blockIdx.z;

    const Ptrs pp = sel.p[fused ? z : 0];
    const float* Ab = A    + (long long)z * sA + (long long)m0 * K;
    const float* Bb = BT ? (pp.B + (long long)z * sB + (long long)n0 * ldb)
                         : (pp.B + (long long)z * sB + n0);
    float*       Cb = pp.C + (long long)z * sC;
    const float* bias = pp.bias;
    const float  scale = pp.scale;

    // 8 A-chunks + 8 B-chunks per thread per stage; offsets recomputed inline
    auto loads = [&](int kt) {
        const uint32_t st = sb + (kt % STG) * STGB;
        const int kof = kt * BK;
        #pragma unroll
        for (int i = 0; i < 8; i++) {                       // A: 128 rows x 8 chunks
            int id = tid + i * 128, r = id >> 3, c = id & 7;
            cp16(st + r * 128 + ((c ^ (r & 7)) * 16), Ab + r * K + kof + c * 4);
        }
        const uint32_t stb = st + A_BY;
        #pragma unroll
        for (int i = 0; i < 8; i++) {
            int id = tid + i * 128;
            if (BT) {
                int r = id >> 3, c = id & 7;
                cp16(stb + r * 128 + ((c ^ (r & 7)) * 16), Bb + r * ldb + kof + c * 4);
            } else {
                int kr = id >> 5, c = id & 31;
                cp16(stb + kr * (BNN_LD * 4) + c * 16,
                     Bb + (long long)(kof + kr) * ldb + c * 4);
            }
        }
        cp_commit();
    };

    float acc[4][NI][4];
    #pragma unroll
    for (int i = 0; i < 4; i++)
        #pragma unroll
        for (int j = 0; j < NI; j++)
            #pragma unroll
            for (int l = 0; l < 4; l++) acc[i][j][l] = 0.f;

    const int NK = K / BK;
    loads(0); loads(1);

    uint32_t af[2][4][4], bf[2][NI][2];

    auto lfA = [&](uint32_t st, int ks, uint32_t f[4][4]) {
        const uint32_t ch0 = ((uint32_t)(2 * ks) ^ (uint32_t)gid) * 16 + tig * 4;
        const uint32_t ch1 = ((uint32_t)(2 * ks + 1) ^ (uint32_t)gid) * 16 + tig * 4;
        #pragma unroll
        for (int mi = 0; mi < 4; mi++) {
            const uint32_t rb = st + (wm + mi * 16 + gid) * 128;
            f[mi][0] = lds32(rb + ch0);
            f[mi][1] = lds32(rb + 8 * 128 + ch0);
            f[mi][2] = lds32(rb + ch1);
            f[mi][3] = lds32(rb + 8 * 128 + ch1);
        }
    };
    auto lfB = [&](uint32_t st, int ks, uint32_t f[NI][2]) {
        const uint32_t stb = st + A_BY;
        if (BT) {
            const uint32_t ch0 = ((uint32_t)(2 * ks) ^ (uint32_t)gid) * 16 + tig * 4;
            const uint32_t ch1 = ((uint32_t)(2 * ks + 1) ^ (uint32_t)gid) * 16 + tig * 4;
            #pragma unroll
            for (int ni = 0; ni < NI; ni++) {
                const uint32_t rb = stb + (wn + ni * 8 + gid) * 128;
                f[ni][0] = lds32(rb + ch0);
                f[ni][1] = lds32(rb + ch1);
            }
        } else {
            const uint32_t rb = stb + (8 * ks + tig) * (BNN_LD * 4) + (wn + gid) * 4;
            #pragma unroll
            for (int ni = 0; ni < NI; ni++) {
                f[ni][0] = lds32(rb + ni * 32);
                f[ni][1] = lds32(rb + 4 * (BNN_LD * 4) + ni * 32);
            }
        }
    };

    for (int kt = 0; kt < NK; kt++) {
        cp_wait1();                       // stage kt landed
        __syncthreads();                  // stage kt-1 fully consumed by all warps

        const uint32_t st = sb + (kt % STG) * STGB;

        lfA(st, 0, af[0]); lfB(st, 0, bf[0]);   // frag buffer 0 first (critical path)
        if (kt + 2 < NK) loads(kt + 2);         // refill stage (kt+2)%3 == (kt-1)%3
        else cp_commit();                       // keep group accounting uniform

        #pragma unroll
        for (int ks = 0; ks < 4; ks++) {
            const int cur = ks & 1, nxt = cur ^ 1;
            if (ks < 3) { lfA(st, ks + 1, af[nxt]); lfB(st, ks + 1, bf[nxt]); }
            #pragma unroll
            for (int mi = 0; mi < 4; mi++)
                #pragma unroll
                for (int ni = 0; ni < NI; ni++)
                    mma8(acc[mi][ni], af[cur][mi], bf[cur][ni]);
        }
    }

    // ---- epilogue: bias + scale + optional tf32 round, float2 stores ----
    #pragma unroll
    for (int mi = 0; mi < 4; mi++) {
        const int r = m0 + wm + mi * 16 + gid;
        #pragma unroll
        for (int ni = 0; ni < NI; ni++) {
            const int c = n0 + wn + ni * 8 + tig * 2;
            float b0 = 0.f, b1 = 0.f;
            if (bias) { b0 = bias[c]; b1 = bias[c + 1]; }
            float v0 = (acc[mi][ni][0] + b0) * scale;
            float v1 = (acc[mi][ni][1] + b1) * scale;
            float v2 = (acc[mi][ni][2] + b0) * scale;
            float v3 = (acc[mi][ni][3] + b1) * scale;
            if (round_out) { v0 = tf32r(v0); v1 = tf32r(v1); v2 = tf32r(v2); v3 = tf32r(v3); }
            *(float2*)(Cb + (long long)r * ldc + c)       = make_float2(v0, v1);
            *(float2*)(Cb + (long long)(r + 8) * ldc + c) = make_float2(v2, v3);
        }
    }
}

constexpr int SM_TN = STG * (A_BY + BTN_BY);   // 98304  (x2 CTAs = 192 KiB/SM)
constexpr int SM_NN = STG * (A_BY + BNN_BY);   // 101376 (x2 CTAs = 198 KiB/SM)

// ---------------------------------------------------------------------------
// Fused tf32 rounding of seq + Wq + Wk + Wv (single launch)
// ---------------------------------------------------------------------------
__global__ void __launch_bounds__(256)
round_all(const float4* __restrict__ seq, const float4* __restrict__ wq,
          const float4* __restrict__ wk,  const float4* __restrict__ wv,
          float4* __restrict__ sr, float4* __restrict__ wr)
{
    constexpr int NSEQ = MTOT * D_MODEL / 4;     // 4194304
    constexpr int NW   = FF * D_MODEL / 4;       // 262144
    constexpr int TOT  = NSEQ + 3 * NW;
    for (int i = blockIdx.x * 256 + threadIdx.x; i < TOT; i += gridDim.x * 256) {
        float4 v;
        float4* dst;
        if (i < NSEQ) { v = seq[i]; dst = sr + i; }
        else {
            int j = i - NSEQ, w = j / NW, o = j - w * NW;
            v = (w == 0) ? wq[o] : (w == 1) ? wk[o] : wv[o];
            dst = wr + j;
        }
        v.x = tf32r(v.x); v.y = tf32r(v.y); v.z = tf32r(v.z); v.w = tf32r(v.w);
        *dst = v;
    }
}

// ---------------------------------------------------------------------------
// Row softmax over 2048 cols; output tf32-rounded (feeds PV GEMM).
// ---------------------------------------------------------------------------
__global__ void __launch_bounds__(256)
softmax_tf32(float* __restrict__ S)
{
    __shared__ float red[8];
    float* row = S + (long long)blockIdx.x * SEQ;
    const int tid = threadIdx.x;

    float4 a = ((float4*)row)[tid];
    float4 b = ((float4*)row)[tid + 256];

    float m = fmaxf(fmaxf(fmaxf(a.x, a.y), fmaxf(a.z, a.w)),
                    fmaxf(fmaxf(b.x, b.y), fmaxf(b.z, b.w)));
    #pragma unroll
    for (int o = 16; o > 0; o >>= 1) m = fmaxf(m, __shfl_xor_sync(0xffffffffu, m, o));
    if ((tid & 31) == 0) red[tid >> 5] = m;
    __syncthreads();
    m = red[0];
    #pragma unroll
    for (int i = 1; i < 8; i++) m = fmaxf(m, red[i]);
    __syncthreads();

    a.x = __expf(a.x - m); a.y = __expf(a.y - m); a.z = __expf(a.z - m); a.w = __expf(a.w - m);
    b.x = __expf(b.x - m); b.y = __expf(b.y - m); b.z = __expf(b.z - m); b.w = __expf(b.w - m);
    float s = a.x + a.y + a.z + a.w + b.x + b.y + b.z + b.w;
    #pragma unroll
    for (int o = 16; o > 0; o >>= 1) s += __shfl_xor_sync(0xffffffffu, s, o);
    if ((tid & 31) == 0) red[tid >> 5] = s;
    __syncthreads();
    s = red[0] + red[1] + red[2] + red[3] + red[4] + red[5] + red[6] + red[7];
    const float inv = 1.0f / s;

    a.x = tf32r(a.x * inv); a.y = tf32r(a.y * inv); a.z = tf32r(a.z * inv); a.w = tf32r(a.w * inv);
    b.x = tf32r(b.x * inv); b.y = tf32r(b.y * inv); b.z = tf32r(b.z * inv); b.w = tf32r(b.w * inv);
    ((float4*)row)[tid]       = a;
    ((float4*)row)[tid + 256] = b;
}

// ---------------------------------------------------------------------------
// kernel_launch — graph-capturable, allocation-free.
// Inputs: 0=sequence, 1=Wq, 2=bq, 3=Wk, 4=bk, 5=Wv, 6=bv. Output fp32.
// ---------------------------------------------------------------------------
extern "C" void kernel_launch(void* const* d_in, const int* in_sizes, int n_in,
                              void* d_out, int out_size)
{
    const float* seq = (const float*)d_in[0];
    const float* Wq  = (const float*)d_in[1];
    const float* bq  = (const float*)d_in[2];
    const float* Wk  = (const float*)d_in[3];
    const float* bk  = (const float*)d_in[4];
    const float* Wv  = (const float*)d_in[5];
    const float* bv  = (const float*)d_in[6];
    float* out = (float*)d_out;

    float *SR, *WR, *Qp, *Kp, *Vp, *Sp;
    cudaGetSymbolAddress((void**)&SR, g_SR);
    cudaGetSymbolAddress((void**)&WR, g_WR);
    cudaGetSymbolAddress((void**)&Qp, g_Q);
    cudaGetSymbolAddress((void**)&Kp, g_K);
    cudaGetSymbolAddress((void**)&Vp, g_V);
    cudaGetSymbolAddress((void**)&Sp, g_S);

    cudaFuncSetAttribute(gemm6<true>,  cudaFuncAttributeMaxDynamicSharedMemorySize, SM_TN);
    cudaFuncSetAttribute(gemm6<false>, cudaFuncAttributeMaxDynamicSharedMemorySize, SM_NN);

    const dim3 blk(128);
    const size_t WSZ = (size_t)FF * D_MODEL;

    // 0) fused tf32 rounding of all inputs
    round_all<<<2048, 256>>>((const float4*)seq, (const float4*)Wq,
                             (const float4*)Wk, (const float4*)Wv,
                             (float4*)SR, (float4*)WR);

    // 1) fused QKV projections: z selects {W, bias, out, scale}; grid (8,128,3)
    {
        Sel s;
        s.p[0] = { WR + 0 * WSZ, bq, Qp, ATTN_SCALE };
        s.p[1] = { WR + 1 * WSZ, bk, Kp, 1.0f };
        s.p[2] = { WR + 2 * WSZ, bv, Vp, 1.0f };
        const dim3 gp(FF / BN, MTOT / BM, 3);
        gemm6<true><<<gp, blk, SM_TN>>>(SR, s, 1, D_MODEL, D_MODEL, FF,
                                        0, 0, 0, 1);
    }

    const long long sQK = (long long)SEQ * FF;
    const long long sS  = (long long)SEQ * SEQ;

    // 2) scores: per batch [2048,2048] = Q @ K^T; grid (16,16,8)
    {
        Sel s; s.p[0] = { Kp, nullptr, Sp, 1.0f };
        const dim3 gs(SEQ / BN, SEQ / BM, NB);
        gemm6<true><<<gs, blk, SM_TN>>>(Qp, s, 0, FF, FF, SEQ,
                                        sQK, sQK, sS, 0);
    }

    // 3) softmax (rounds P to tf32)
    softmax_tf32<<<MTOT, 256>>>(Sp);

    // 4) output: per batch [2048,1024] = P @ V; grid (8,16,8)
    {
        Sel s; s.p[0] = { Vp, nullptr, out, 1.0f };
        const dim3 go(FF / BN, SEQ / BM, NB);
        gemm6<false><<<go, blk, SM_NN>>>(Sp, s, 0, SEQ, FF, FF,
                                         sS, sQK, sQK, 0);
    }
}